// round 4
// baseline (speedup 1.0000x reference)
#include <cuda_runtime.h>
#include <cuda_fp16.h>
#include <cstdint>
#include <math.h>

#define GD 1935      // GATE_DIM
#define OPAD 304     // padded 300 (=19*16)
#define PCOLS 320    // fc3h padded p cols

// ------------------------- device scratch (no allocs) -----------------------
__device__ __align__(16) float  g_sg1[GD];
__device__ __align__(16) float  g_sg2[GD];
__device__ __align__(16) float  g_f[768 * 300];          // gated features @ attr
__device__ __align__(16) __half g_Uh[384 * OPAD];
__device__ __align__(16) __half g_Vh[384 * OPAD];
__device__ __align__(16) __half g_Ph[384 * OPAD];
__device__ __align__(16) __half g_Qh[384 * OPAD];
__device__ __align__(16) float  g_fc1ta[300 * OPAD];     // [d][o] = fc1_w[o][d]
__device__ __align__(16) float  g_fc1tb[300 * OPAD];     // [d][o] = fc1_w[o][300+d]
__device__ __align__(16) __half g_fc3h[OPAD * PCOLS];    // [o][p] = fc3_w[p][o]

// ------------------------------ mma helpers ---------------------------------
__device__ __forceinline__ void ldsm_x4(uint32_t a, uint32_t& r0, uint32_t& r1,
                                        uint32_t& r2, uint32_t& r3) {
    asm volatile("ldmatrix.sync.aligned.m8n8.x4.shared.b16 {%0,%1,%2,%3}, [%4];"
                 : "=r"(r0), "=r"(r1), "=r"(r2), "=r"(r3) : "r"(a));
}
__device__ __forceinline__ void ldsm_x4t(uint32_t a, uint32_t& r0, uint32_t& r1,
                                         uint32_t& r2, uint32_t& r3) {
    asm volatile("ldmatrix.sync.aligned.m8n8.x4.trans.shared.b16 {%0,%1,%2,%3}, [%4];"
                 : "=r"(r0), "=r"(r1), "=r"(r2), "=r"(r3) : "r"(a));
}
__device__ __forceinline__ void mma16816(float* c, const uint32_t* a, uint32_t b0, uint32_t b1) {
    asm volatile(
        "mma.sync.aligned.m16n8k16.row.col.f32.f16.f16.f32 "
        "{%0,%1,%2,%3},{%4,%5,%6,%7},{%8,%9},{%0,%1,%2,%3};"
        : "+f"(c[0]), "+f"(c[1]), "+f"(c[2]), "+f"(c[3])
        : "r"(a[0]), "r"(a[1]), "r"(a[2]), "r"(a[3]), "r"(b0), "r"(b1));
}

// ------------------------------- K0: prep ----------------------------------
__global__ void k0_prep(const float* __restrict__ gate1, const float* __restrict__ gate2,
                        const float* __restrict__ fc3w, const float* __restrict__ fc1w,
                        const float* __restrict__ box1, const float* __restrict__ box2,
                        const float* __restrict__ fc2w, const float* __restrict__ fc2b) {
    int i = blockIdx.x * 256 + threadIdx.x;
    if (i < GD) {
        g_sg1[i] = 1.f / (1.f + expf(-gate1[i]));
        g_sg2[i] = 1.f / (1.f + expf(-gate2[i]));
    }
    if (i < OPAD * PCOLS) {               // fc3h[o][p] = fc3_w[p][o]
        int o = i / PCOLS, p = i - o * PCOLS;
        float v = (o < 300 && p < 300) ? fc3w[p * 300 + o] : 0.f;
        g_fc3h[i] = __float2half_rn(v);
    }
    if (i < 300 * OPAD) {                 // fc1t[d][o]
        int d = i / OPAD, o = i - d * OPAD;
        g_fc1ta[i] = (o < 300) ? fc1w[o * 600 + d] : 0.f;
        g_fc1tb[i] = (o < 300) ? fc1w[o * 600 + 300 + d] : 0.f;
    }
    if (i < 384 * OPAD) {                 // spatial P/Q (K=5), stored fp16
        int n = i / OPAD, o = i - n * OPAD;
        float pv = 0.f, qv = 0.f;
        if (o < 300) {
#pragma unroll
            for (int j = 0; j < 5; j++) {
                pv += box1[n * 5 + j] * fc2w[o * 10 + j];
                qv += box2[n * 5 + j] * fc2w[o * 10 + 5 + j];
            }
            pv += fc2b[o];
        }
        g_Ph[i] = __float2half_rn(pv);
        g_Qh[i] = __float2half_rn(qv);
    }
}

// ------ K1: f[768,300] = (feature .* sig(gate)) @ attr, fp16 tensor --------
// block: 128 threads (4 warps), tile 64 rows x 32 cols, K chunks of 64 (31)
__global__ __launch_bounds__(128) void k1_feat(const float* __restrict__ f1,
                                               const float* __restrict__ f2,
                                               const float* __restrict__ attr) {
    __shared__ __half Af[64 * 72];
    __shared__ __half Bf[64 * 40];
    int tid = threadIdx.x, lane = tid & 31, w = tid >> 5;
    int r0 = blockIdx.x * 64, c0 = blockIdx.y * 32;
    const float* fptr = (r0 < 384) ? f1 : f2;
    int rbase = (r0 < 384) ? r0 : r0 - 384;
    const float* sg = (r0 < 384) ? g_sg1 : g_sg2;

    float acc[4][4] = {};
    uint32_t sa = (uint32_t)__cvta_generic_to_shared(Af);
    uint32_t sbB = (uint32_t)__cvta_generic_to_shared(Bf);
    uint32_t aAddr = sa + ((w * 16 + (lane & 15)) * 72 + (lane >> 4) * 8) * 2;
    uint32_t bAddr = sbB + ((lane & 15) * 40 + (lane >> 4) * 8) * 2;

    for (int kc = 0; kc < 31; ++kc) {
        int k0 = kc * 64;
        __syncthreads();
        // stage A (64x64, gated, fp16)
        for (int h = tid; h < 64 * 32; h += 128) {
            int r = h >> 5, k2 = (h & 31) * 2, gk = k0 + k2;
            int grow = rbase + r;
            float a0 = (gk < GD) ? fptr[(size_t)grow * GD + gk] * sg[gk] : 0.f;
            float a1 = (gk + 1 < GD) ? fptr[(size_t)grow * GD + gk + 1] * sg[gk + 1] : 0.f;
            *(half2*)&Af[r * 72 + k2] = __floats2half2_rn(a0, a1);
        }
        // stage B (64x32)
        for (int h = tid; h < 64 * 16; h += 128) {
            int k = h >> 4, c2 = (h & 15) * 2, gk = k0 + k, gc = c0 + c2;
            float b0 = (gk < GD && gc < 300) ? attr[(size_t)gk * 300 + gc] : 0.f;
            float b1 = (gk < GD && gc + 1 < 300) ? attr[(size_t)gk * 300 + gc + 1] : 0.f;
            *(half2*)&Bf[k * 40 + c2] = __floats2half2_rn(b0, b1);
        }
        __syncthreads();
#pragma unroll
        for (int ks = 0; ks < 4; ++ks) {
            uint32_t a[4];
            ldsm_x4(aAddr + ks * 32, a[0], a[1], a[2], a[3]);
            uint32_t b0, b1, b2, b3, c0r, c1r, c2r, c3r;
            ldsm_x4t(bAddr + ks * 1280, b0, b1, b2, b3);
            ldsm_x4t(bAddr + ks * 1280 + 32, c0r, c1r, c2r, c3r);
            mma16816(acc[0], a, b0, b1);
            mma16816(acc[1], a, b2, b3);
            mma16816(acc[2], a, c0r, c1r);
            mma16816(acc[3], a, c2r, c3r);
        }
    }
    int rr = r0 + w * 16 + (lane >> 2);
    int cbase = c0 + 2 * (lane & 3);
#pragma unroll
    for (int j = 0; j < 4; ++j) {
        int col = cbase + j * 8;
        if (col < 300) {
            *(float2*)&g_f[(size_t)rr * 300 + col] = make_float2(acc[j][0], acc[j][1]);
            *(float2*)&g_f[(size_t)(rr + 8) * 300 + col] = make_float2(acc[j][2], acc[j][3]);
        }
    }
}

// --------- K2: U/V[384,304] = f @ fc1t (+fc1_b for U), fp32 -> fp16 --------
__global__ void k2_uv(const float* __restrict__ fc1b) {
    __shared__ float As[32 * 34];
    __shared__ float Bs[32 * 34];
    int tid = threadIdx.x;
    int tx = tid & 15, ty = tid >> 4;
    int r0 = blockIdx.y * 32, c0 = blockIdx.x * 32;
    bool isU = (r0 < 384);
    const float* Bmat = isU ? g_fc1ta : g_fc1tb;
    float a00 = 0.f, a01 = 0.f, a10 = 0.f, a11 = 0.f;
    for (int kt = 0; kt < 10; ++kt) {
        int k0 = kt * 32;
#pragma unroll
        for (int idx = tid; idx < 1024; idx += 256) {
            int r = idx >> 5, k = idx & 31;
            int gk = k0 + k;
            As[k * 34 + r] = (gk < 300) ? g_f[(r0 + r) * 300 + gk] : 0.f;
            int kb = idx >> 5, c = idx & 31;
            int gkb = k0 + kb, gc = c0 + c;
            Bs[kb * 34 + c] = (gkb < 300 && gc < OPAD) ? Bmat[gkb * OPAD + gc] : 0.f;
        }
        __syncthreads();
#pragma unroll
        for (int kk = 0; kk < 32; ++kk) {
            float2 a = *(const float2*)&As[kk * 34 + ty * 2];
            float2 b = *(const float2*)&Bs[kk * 34 + tx * 2];
            a00 += a.x * b.x; a01 += a.x * b.y;
            a10 += a.y * b.x; a11 += a.y * b.y;
        }
        __syncthreads();
    }
    int r = r0 + ty * 2, c = c0 + tx * 2;
    if (c < OPAD) {
        float b0 = 0.f, b1 = 0.f;
        if (isU) {
            if (c < 300) b0 = fc1b[c];
            if (c + 1 < 300) b1 = fc1b[c + 1];
        }
        __half* dst = isU ? g_Uh : g_Vh;
        int rr = isU ? r : r - 384;
        *(half2*)&dst[rr * OPAD + c] = __floats2half2_rn(a00 + b0, a01 + b1);
        *(half2*)&dst[(rr + 1) * OPAD + c] = __floats2half2_rn(a10 + b0, a11 + b1);
    }
}

// ------------------------------- K3: fused main -----------------------------
// 256 threads (8 warps), 2 CTAs/SM. pair tile 8n x 16m; warp w owns n=n0+w.
// p in 10 chunks of 32. A tile rebuilt from fp16 U/V/P/Q (L1-cached).
constexpr int A_STR = 312;
constexpr int B_STR2 = 40;
constexpr int OFF_B3 = 128 * A_STR * 2;                  // 79872
constexpr int OFF_SB3 = OFF_B3 + 304 * B_STR2 * 2;       // 104192
constexpr int SMEM3 = OFF_SB3 + 320 * 4;                 // 105472

__global__ __launch_bounds__(256, 2) void k3_main(const float* __restrict__ wloc,
                                                  const float* __restrict__ fc3b,
                                                  float* __restrict__ out) {
    extern __shared__ char smem[];
    __half* Asm = (__half*)smem;
    __half* Bsm = (__half*)(smem + OFF_B3);
    float* sb = (float*)(smem + OFF_SB3);

    int tid = threadIdx.x, lane = tid & 31, w = tid >> 5;
    int n0 = blockIdx.x * 8, m0 = blockIdx.y * 16;

    for (int i = tid; i < 320; i += 256) sb[i] = (i < 300) ? fc3b[i] : 0.f;

    float l0 = wloc[0], l1 = wloc[1];
    float mx = fmaxf(l0, l1);
    float e0 = expf(l0 - mx), e1 = expf(l1 - mx);
    float w0 = e0 / (e0 + e1), w1 = e1 / (e0 + e1);

    // build A tile (128 x 304) in fp16 from global fp16 U/V/P/Q
    for (int i = tid; i < 128 * 152; i += 256) {
        int pr = i / 152, o2 = (i - pr * 152) * 2;
        int ni = pr >> 4, mi = pr & 15;
        float2 u = __half22float2(*(const half2*)&g_Uh[(n0 + ni) * OPAD + o2]);
        float2 v = __half22float2(*(const half2*)&g_Vh[(m0 + mi) * OPAD + o2]);
        float2 p = __half22float2(*(const half2*)&g_Ph[(n0 + ni) * OPAD + o2]);
        float2 q = __half22float2(*(const half2*)&g_Qh[(m0 + mi) * OPAD + o2]);
        float rA = w0 * fmaxf(u.x + v.x, 0.f) + w1 * fmaxf(p.x + q.x, 0.f);
        float rB = w0 * fmaxf(u.y + v.y, 0.f) + w1 * fmaxf(p.y + q.y, 0.f);
        *(half2*)&Asm[pr * A_STR + o2] = __floats2half2_rn(rA, rB);
    }
    __syncthreads();

    uint32_t sbase = (uint32_t)__cvta_generic_to_shared(smem);
    uint32_t aAddr = sbase + ((w * 16 + (lane & 15)) * A_STR + (lane >> 4) * 8) * 2;
    uint32_t bAddr = sbase + OFF_B3 + ((lane & 15) * B_STR2 + (lane >> 4) * 8) * 2;
    int r1l = lane >> 2, cb = 2 * (lane & 3);
    int n = n0 + w;

    for (int pc = 0; pc < 10; ++pc) {
        int p0 = pc * 32;
        __syncthreads();
        for (int i = tid; i < 304 * 16; i += 256) {
            int row = i >> 4, c2 = (i & 15) * 2;
            *(half2*)&Bsm[row * B_STR2 + c2] =
                *(const half2*)&g_fc3h[row * PCOLS + p0 + c2];
        }
        __syncthreads();

        float acc[4][4] = {};
#pragma unroll
        for (int ks = 0; ks < 19; ++ks) {
            uint32_t a[4];
            ldsm_x4(aAddr + ks * 32, a[0], a[1], a[2], a[3]);
            uint32_t b0, b1, b2, b3, c0r, c1r, c2r, c3r;
            ldsm_x4t(bAddr + ks * (16 * B_STR2 * 2), b0, b1, b2, b3);
            ldsm_x4t(bAddr + ks * (16 * B_STR2 * 2) + 32, c0r, c1r, c2r, c3r);
            mma16816(acc[0], a, b0, b1);
            mma16816(acc[1], a, b2, b3);
            mma16816(acc[2], a, c0r, c1r);
            mma16816(acc[3], a, c2r, c3r);
        }
#pragma unroll
        for (int j = 0; j < 4; ++j) {
            int col = p0 + j * 8 + cb;
            if (col < 300) {
                size_t base1 = ((size_t)n * 384 + (m0 + r1l)) * 300 + col;
                size_t base2 = ((size_t)n * 384 + (m0 + r1l + 8)) * 300 + col;
                *(float2*)&out[base1] = make_float2(acc[j][0] + sb[col], acc[j][1] + sb[col + 1]);
                *(float2*)&out[base2] = make_float2(acc[j][2] + sb[col], acc[j][3] + sb[col + 1]);
            }
        }
    }
}

// ------------------------------- launch -------------------------------------
extern "C" void kernel_launch(void* const* d_in, const int* in_sizes, int n_in,
                              void* d_out, int out_size) {
    const float* feature1 = (const float*)d_in[0];
    const float* box1     = (const float*)d_in[1];
    const float* feature2 = (const float*)d_in[2];
    const float* box2     = (const float*)d_in[3];
    const float* attr     = (const float*)d_in[4];
    const float* gate1    = (const float*)d_in[5];
    const float* gate2    = (const float*)d_in[6];
    const float* wloc     = (const float*)d_in[7];
    const float* fc1_b    = (const float*)d_in[9];
    const float* fc1_w    = (const float*)d_in[8];
    const float* fc2_w    = (const float*)d_in[10];
    const float* fc2_b    = (const float*)d_in[11];
    const float* fc3_w    = (const float*)d_in[12];
    const float* fc3_b    = (const float*)d_in[13];
    float* out = (float*)d_out;

    static bool attr_set = false;
    if (!attr_set) {
        cudaFuncSetAttribute(k3_main, cudaFuncAttributeMaxDynamicSharedMemorySize, SMEM3);
        attr_set = true;
    }

    k0_prep<<<456, 256>>>(gate1, gate2, fc3_w, fc1_w, box1, box2, fc2_w, fc2_b);
    k1_feat<<<dim3(12, 10), 128>>>(feature1, feature2, attr);
    k2_uv<<<dim3(10, 24), 256>>>(fc1_b);
    k3_main<<<dim3(48, 24), 256, SMEM3>>>(wloc, fc3_b, out);
}

// round 6
// speedup vs baseline: 1.7194x; 1.7194x over previous
#include <cuda_runtime.h>
#include <cuda_fp16.h>
#include <cstdint>
#include <math.h>

#define GD 1935       // GATE_DIM
#define OPAD 304      // padded 300 for U/V/P/Q (19*16)
#define KPAD 2048     // padded GATE_DIM for fp16 gemm
#define NPAD 320      // padded 300 cols (attr)
#define P3PAD 384     // fc3 p cols padded to 3*128

// ------------------------- device scratch (no allocs) -----------------------
__device__ __align__(16) __half g_gf[768 * KPAD];       // gated features fp16
__device__ __align__(16) __half g_attrh[KPAD * NPAD];   // attr fp16 [k][n]
__device__ __align__(16) __half g_fc3t[OPAD * P3PAD];   // [o][p] fp16
__device__ __align__(16) float  g_f [768 * 300];        // k1 partial (z=0)
__device__ __align__(16) float  g_f2[768 * 300];        // k1 partial (z=1)
__device__ __align__(16) float  g_fc1ta[300 * OPAD];    // [d][o] = fc1_w[o][d]
__device__ __align__(16) float  g_fc1tb[300 * OPAD];    // [d][o] = fc1_w[o][300+d]
__device__ __align__(16) __half g_Uh[384 * OPAD];
__device__ __align__(16) __half g_Vh[384 * OPAD];
__device__ __align__(16) __half g_Ph[384 * OPAD];
__device__ __align__(16) __half g_Qh[384 * OPAD];

// ------------------------------ helpers -------------------------------------
__device__ __forceinline__ void ldsm_x4(uint32_t a, uint32_t& r0, uint32_t& r1,
                                        uint32_t& r2, uint32_t& r3) {
    asm volatile("ldmatrix.sync.aligned.m8n8.x4.shared.b16 {%0,%1,%2,%3}, [%4];"
                 : "=r"(r0), "=r"(r1), "=r"(r2), "=r"(r3) : "r"(a));
}
__device__ __forceinline__ void ldsm_x4t(uint32_t a, uint32_t& r0, uint32_t& r1,
                                         uint32_t& r2, uint32_t& r3) {
    asm volatile("ldmatrix.sync.aligned.m8n8.x4.trans.shared.b16 {%0,%1,%2,%3}, [%4];"
                 : "=r"(r0), "=r"(r1), "=r"(r2), "=r"(r3) : "r"(a));
}
__device__ __forceinline__ void mma16816(float* c, const uint32_t* a, uint32_t b0, uint32_t b1) {
    asm volatile(
        "mma.sync.aligned.m16n8k16.row.col.f32.f16.f16.f32 "
        "{%0,%1,%2,%3},{%4,%5,%6,%7},{%8,%9},{%0,%1,%2,%3};"
        : "+f"(c[0]), "+f"(c[1]), "+f"(c[2]), "+f"(c[3])
        : "r"(a[0]), "r"(a[1]), "r"(a[2]), "r"(a[3]), "r"(b0), "r"(b1));
}
__device__ __forceinline__ uint32_t cvta_s(const void* p) {
    uint32_t a;
    asm("{ .reg .u64 t; cvta.to.shared.u64 t, %1; cvt.u32.u64 %0, t; }"
        : "=r"(a) : "l"(p));
    return a;
}

// ------------------------------- K0: prep ----------------------------------
__global__ void k0_prep(const float* __restrict__ f1, const float* __restrict__ f2,
                        const float* __restrict__ gate1, const float* __restrict__ gate2,
                        const float* __restrict__ attr,
                        const float* __restrict__ fc3w, const float* __restrict__ fc1w,
                        const float* __restrict__ box1, const float* __restrict__ box2,
                        const float* __restrict__ fc2w, const float* __restrict__ fc2b) {
    int i = blockIdx.x * 256 + threadIdx.x;
    // gated features fp16: [768][2048]
    if (i < 768 * KPAD) {
        int r = i >> 11, k = i & (KPAD - 1);
        float v = 0.f;
        if (k < GD) {
            float g = (r < 384) ? gate1[k] : gate2[k];
            float s = 1.f / (1.f + expf(-g));
            v = ((r < 384) ? f1[(size_t)r * GD + k] : f2[(size_t)(r - 384) * GD + k]) * s;
        }
        g_gf[i] = __float2half_rn(v);
    }
    // attr fp16: [2048][320]
    if (i < KPAD * NPAD) {
        int k = i / NPAD, n = i - k * NPAD;
        g_attrh[i] = __float2half_rn((k < GD && n < 300) ? attr[(size_t)k * 300 + n] : 0.f);
    }
    // fc3t fp16: [304 o][384 p], fc3t[o][p] = fc3_w[p][o]
    if (i < OPAD * P3PAD) {
        int o = i / P3PAD, p = i - o * P3PAD;
        g_fc3t[i] = __float2half_rn((o < 300 && p < 300) ? fc3w[p * 300 + o] : 0.f);
    }
    // fc1t [d][o]
    if (i < 300 * OPAD) {
        int d = i / OPAD, o = i - d * OPAD;
        g_fc1ta[i] = (o < 300) ? fc1w[o * 600 + d] : 0.f;
        g_fc1tb[i] = (o < 300) ? fc1w[o * 600 + 300 + d] : 0.f;
    }
    // spatial P/Q fp16
    if (i < 384 * OPAD) {
        int n = i / OPAD, o = i - n * OPAD;
        float pv = 0.f, qv = 0.f;
        if (o < 300) {
#pragma unroll
            for (int j = 0; j < 5; j++) {
                pv += box1[n * 5 + j] * fc2w[o * 10 + j];
                qv += box2[n * 5 + j] * fc2w[o * 10 + 5 + j];
            }
            pv += fc2b[o];
        }
        g_Ph[i] = __float2half_rn(pv);
        g_Qh[i] = __float2half_rn(qv);
    }
}

// ---- K1: partial f = gf @ attrh, fp16 mma, tile 64x64, K-split 2 ----------
__global__ __launch_bounds__(256) void k1_feat() {
    __shared__ __half Af[64 * 72];
    __shared__ __half Bf[64 * 72];
    int tid = threadIdx.x, lane = tid & 31, w = tid >> 5;
    int wm = w >> 1, wn = w & 1;
    int r0 = blockIdx.x * 64, c0 = blockIdx.y * 64;
    int zoff = blockIdx.z * 1024;
    float acc[4][4] = {};
    uint32_t sa = cvta_s(Af), sbB = cvta_s(Bf);
    uint32_t aAddr = sa + ((wm * 16 + (lane & 15)) * 72 + (lane >> 4) * 8) * 2;
    uint32_t bAddr = sbB + ((lane & 15) * 72 + wn * 32 + (lane >> 4) * 8) * 2;

    for (int kc = 0; kc < 16; ++kc) {
        int k0 = zoff + kc * 64;
        __syncthreads();
        for (int i = tid; i < 512; i += 256) {
            int r = i >> 3, u = i & 7;
            *(uint4*)(Af + r * 72 + u * 8) =
                *(const uint4*)(g_gf + (size_t)(r0 + r) * KPAD + k0 + u * 8);
        }
        for (int i = tid; i < 512; i += 256) {
            int k = i >> 3, u = i & 7;
            *(uint4*)(Bf + k * 72 + u * 8) =
                *(const uint4*)(g_attrh + (size_t)(k0 + k) * NPAD + c0 + u * 8);
        }
        __syncthreads();
#pragma unroll
        for (int ks = 0; ks < 4; ++ks) {
            uint32_t a[4];
            ldsm_x4(aAddr + ks * 32, a[0], a[1], a[2], a[3]);
            uint32_t b0, b1, b2, b3, d0, d1, d2, d3;
            ldsm_x4t(bAddr + ks * 2304, b0, b1, b2, b3);
            ldsm_x4t(bAddr + ks * 2304 + 32, d0, d1, d2, d3);
            mma16816(acc[0], a, b0, b1);
            mma16816(acc[1], a, b2, b3);
            mma16816(acc[2], a, d0, d1);
            mma16816(acc[3], a, d2, d3);
        }
    }
    float* dst = blockIdx.z ? g_f2 : g_f;
    int rr = r0 + wm * 16 + (lane >> 2);
    int cbase = c0 + wn * 32 + 2 * (lane & 3);
#pragma unroll
    for (int j = 0; j < 4; ++j) {
        int col = cbase + j * 8;
        if (col < 300) {
            *(float2*)&dst[(size_t)rr * 300 + col] = make_float2(acc[j][0], acc[j][1]);
            *(float2*)&dst[(size_t)(rr + 8) * 300 + col] = make_float2(acc[j][2], acc[j][3]);
        }
    }
}

// --------- K2: U/V[384,304] = (g_f+g_f2) @ fc1t (+fc1_b), fp32 -> fp16 -----
__global__ void k2_uv(const float* __restrict__ fc1b) {
    __shared__ float As[32 * 34];
    __shared__ float Bs[32 * 34];
    int tid = threadIdx.x;
    int tx = tid & 15, ty = tid >> 4;
    int r0 = blockIdx.y * 32, c0 = blockIdx.x * 32;
    bool isU = (r0 < 384);
    const float* Bmat = isU ? g_fc1ta : g_fc1tb;
    float a00 = 0.f, a01 = 0.f, a10 = 0.f, a11 = 0.f;
    for (int kt = 0; kt < 10; ++kt) {
        int k0 = kt * 32;
#pragma unroll
        for (int idx = tid; idx < 1024; idx += 256) {
            int r = idx >> 5, k = idx & 31;
            int gk = k0 + k;
            As[k * 34 + r] = (gk < 300)
                ? g_f[(r0 + r) * 300 + gk] + g_f2[(r0 + r) * 300 + gk] : 0.f;
            int kb = idx >> 5, c = idx & 31;
            int gkb = k0 + kb, gc = c0 + c;
            Bs[kb * 34 + c] = (gkb < 300 && gc < OPAD) ? Bmat[gkb * OPAD + gc] : 0.f;
        }
        __syncthreads();
#pragma unroll
        for (int kk = 0; kk < 32; ++kk) {
            float2 a = *(const float2*)&As[kk * 34 + ty * 2];
            float2 b = *(const float2*)&Bs[kk * 34 + tx * 2];
            a00 += a.x * b.x; a01 += a.x * b.y;
            a10 += a.y * b.x; a11 += a.y * b.y;
        }
        __syncthreads();
    }
    int r = r0 + ty * 2, c = c0 + tx * 2;
    if (c < OPAD) {
        float b0 = 0.f, b1 = 0.f;
        if (isU) {
            if (c < 300) b0 = fc1b[c];
            if (c + 1 < 300) b1 = fc1b[c + 1];
        }
        __half* dst = isU ? g_Uh : g_Vh;
        int rr = isU ? r : r - 384;
        *(half2*)&dst[rr * OPAD + c] = __floats2half2_rn(a00 + b0, a01 + b1);
        *(half2*)&dst[(rr + 1) * OPAD + c] = __floats2half2_rn(a10 + b0, a11 + b1);
    }
}

// ------------------------------- K3: fused main -----------------------------
// 256 thr, 8 warps = 4 row-groups x 2 col-groups; warp tile 32 pairs x 64 p.
// pair tile 128 (8n x 16m). p in 3 chunks of 128. K = o, 19 steps of 16.
constexpr int A_STR = 312;                       // halves
constexpr int B_STR3 = 136;                      // halves
constexpr int OFF_A3 = 1536;                     // after 320*4 bias + pad
constexpr int OFF_B3 = OFF_A3 + 128 * A_STR * 2; // 81408
constexpr int K3_SMEM = OFF_B3 + OPAD * B_STR3 * 2;  // 164096

__global__ __launch_bounds__(256, 1) void k3_main(const float* __restrict__ wloc,
                                                  const float* __restrict__ fc3b,
                                                  float* __restrict__ out) {
    extern __shared__ char smem[];
    float* sbias = (float*)smem;
    __half* Asm = (__half*)(smem + OFF_A3);
    __half* Bsm = (__half*)(smem + OFF_B3);

    int tid = threadIdx.x, lane = tid & 31, w = tid >> 5;
    int wr = w & 3, wc = w >> 2;
    int n0 = blockIdx.x * 8, m0 = blockIdx.y * 16;

    for (int i = tid; i < 320; i += 256) sbias[i] = (i < 300) ? fc3b[i] : 0.f;

    float l0 = wloc[0], l1 = wloc[1];
    float mx = fmaxf(l0, l1);
    float e0 = expf(l0 - mx), e1 = expf(l1 - mx);
    float w0 = e0 / (e0 + e1), w1 = e1 / (e0 + e1);

    // build A tile (128 pairs x 304 k) fp16 from U/V/P/Q
    for (int i = tid; i < 128 * 152; i += 256) {
        int pr = i / 152, o2 = (i - pr * 152) * 2;
        int ni = pr >> 4, mi = pr & 15;
        float2 u = __half22float2(*(const half2*)&g_Uh[(n0 + ni) * OPAD + o2]);
        float2 v = __half22float2(*(const half2*)&g_Vh[(m0 + mi) * OPAD + o2]);
        float2 p = __half22float2(*(const half2*)&g_Ph[(n0 + ni) * OPAD + o2]);
        float2 q = __half22float2(*(const half2*)&g_Qh[(m0 + mi) * OPAD + o2]);
        float rA = w0 * fmaxf(u.x + v.x, 0.f) + w1 * fmaxf(p.x + q.x, 0.f);
        float rB = w0 * fmaxf(u.y + v.y, 0.f) + w1 * fmaxf(p.y + q.y, 0.f);
        *(half2*)&Asm[pr * A_STR + o2] = __floats2half2_rn(rA, rB);
    }

    uint32_t sbase = cvta_s(smem);
    uint32_t aAddr = sbase + OFF_A3 +
                     ((wr * 32 + (lane & 15)) * A_STR + (lane >> 4) * 8) * 2;
    uint32_t bAddr = sbase + OFF_B3 +
                     ((lane & 15) * B_STR3 + wc * 64 + (lane >> 4) * 8) * 2;
    int rbase = lane >> 2, cb = 2 * (lane & 3);

    for (int pc = 0; pc < 3; ++pc) {
        int p0 = pc * 128;
        __syncthreads();  // A ready (pc=0) / prior B reads done
        for (int i = tid; i < 304 * 16; i += 256) {
            int row = i >> 4, u = i & 15;
            *(uint4*)(Bsm + row * B_STR3 + u * 8) =
                *(const uint4*)(g_fc3t + (size_t)row * P3PAD + p0 + u * 8);
        }
        __syncthreads();

        float acc[2][8][4];
#pragma unroll
        for (int x = 0; x < 2; x++)
#pragma unroll
            for (int y = 0; y < 8; y++)
#pragma unroll
                for (int z = 0; z < 4; z++) acc[x][y][z] = 0.f;

        for (int ks = 0; ks < 19; ++ks) {
            uint32_t a0[4], a1[4];
            ldsm_x4(aAddr + ks * 32, a0[0], a0[1], a0[2], a0[3]);
            ldsm_x4(aAddr + 16 * A_STR * 2 + ks * 32, a1[0], a1[1], a1[2], a1[3]);
            uint32_t bofs = bAddr + ks * (16 * B_STR3 * 2);
#pragma unroll
            for (int g = 0; g < 4; ++g) {
                uint32_t b0, b1, b2, b3;
                ldsm_x4t(bofs + g * 32, b0, b1, b2, b3);
                mma16816(acc[0][2 * g],     a0, b0, b1);
                mma16816(acc[0][2 * g + 1], a0, b2, b3);
                mma16816(acc[1][2 * g],     a1, b0, b1);
                mma16816(acc[1][2 * g + 1], a1, b2, b3);
            }
        }

        // epilogue: rows = wr*32 + i*16 + rbase (+8), cols = p0 + wc*64 + j*8 + cb
#pragma unroll
        for (int i2 = 0; i2 < 2; ++i2) {
            int pr = wr * 32 + i2 * 16 + rbase;
            int ni = pr >> 4, mi = pr & 15;
            size_t ob1 = ((size_t)(n0 + ni) * 384 + (m0 + mi)) * 300;
            int pr2 = pr + 8;
            int ni2 = pr2 >> 4, mi2 = pr2 & 15;
            size_t ob2 = ((size_t)(n0 + ni2) * 384 + (m0 + mi2)) * 300;
#pragma unroll
            for (int j = 0; j < 8; ++j) {
                int col = p0 + wc * 64 + j * 8 + cb;
                if (col < 300) {
                    *(float2*)&out[ob1 + col] =
                        make_float2(acc[i2][j][0] + sbias[col], acc[i2][j][1] + sbias[col + 1]);
                    *(float2*)&out[ob2 + col] =
                        make_float2(acc[i2][j][2] + sbias[col], acc[i2][j][3] + sbias[col + 1]);
                }
            }
        }
    }
}

// ------------------------------- launch -------------------------------------
extern "C" void kernel_launch(void* const* d_in, const int* in_sizes, int n_in,
                              void* d_out, int out_size) {
    const float* feature1 = (const float*)d_in[0];
    const float* box1     = (const float*)d_in[1];
    const float* feature2 = (const float*)d_in[2];
    const float* box2     = (const float*)d_in[3];
    const float* attr     = (const float*)d_in[4];
    const float* gate1    = (const float*)d_in[5];
    const float* gate2    = (const float*)d_in[6];
    const float* wloc     = (const float*)d_in[7];
    const float* fc1_w    = (const float*)d_in[8];
    const float* fc1_b    = (const float*)d_in[9];
    const float* fc2_w    = (const float*)d_in[10];
    const float* fc2_b    = (const float*)d_in[11];
    const float* fc3_w    = (const float*)d_in[12];
    const float* fc3_b    = (const float*)d_in[13];
    float* out = (float*)d_out;

    static bool attr_set = false;
    if (!attr_set) {
        cudaFuncSetAttribute(k3_main, cudaFuncAttributeMaxDynamicSharedMemorySize, K3_SMEM);
        attr_set = true;
    }

    k0_prep<<<6144, 256>>>(feature1, feature2, gate1, gate2, attr,
                           fc3_w, fc1_w, box1, box2, fc2_w, fc2_b);
    k1_feat<<<dim3(12, 5, 2), 256>>>();
    k2_uv<<<dim3(10, 24), 256>>>(fc1_b);
    k3_main<<<dim3(48, 24), 256, K3_SMEM>>>(wloc, fc3_b, out);
}

// round 7
// speedup vs baseline: 1.8658x; 1.0851x over previous
#include <cuda_runtime.h>
#include <cuda_fp16.h>
#include <cstdint>
#include <math.h>

#define GD 1935       // GATE_DIM
#define OPAD 304      // padded 300 for U/V/P/Q (19*16)
#define KPAD 2048     // padded GATE_DIM for fp16 gemm
#define NPAD 320      // padded 300 cols (attr)
#define P3PAD 320     // fc3 p cols padded

// ------------------------- device scratch (no allocs) -----------------------
__device__ __align__(16) __half g_gf[768 * KPAD];       // gated features fp16
__device__ __align__(16) __half g_attrh[KPAD * NPAD];   // attr fp16 [k][n]
__device__ __align__(16) __half g_fc3t[OPAD * P3PAD];   // [o][p] fp16
__device__ __align__(16) float  g_f [768 * 300];        // k1 partial (z=0)
__device__ __align__(16) float  g_f2[768 * 300];        // k1 partial (z=1)
__device__ __align__(16) float  g_fc1ta[300 * OPAD];    // [d][o] = fc1_w[o][d]
__device__ __align__(16) float  g_fc1tb[300 * OPAD];    // [d][o] = fc1_w[o][300+d]
__device__ __align__(16) __half g_Uh[384 * OPAD];
__device__ __align__(16) __half g_Vh[384 * OPAD];
__device__ __align__(16) __half g_Ph[384 * OPAD];
__device__ __align__(16) __half g_Qh[384 * OPAD];

// ------------------------------ helpers -------------------------------------
__device__ __forceinline__ void ldsm_x4(uint32_t a, uint32_t& r0, uint32_t& r1,
                                        uint32_t& r2, uint32_t& r3) {
    asm volatile("ldmatrix.sync.aligned.m8n8.x4.shared.b16 {%0,%1,%2,%3}, [%4];"
                 : "=r"(r0), "=r"(r1), "=r"(r2), "=r"(r3) : "r"(a));
}
__device__ __forceinline__ void ldsm_x4t(uint32_t a, uint32_t& r0, uint32_t& r1,
                                         uint32_t& r2, uint32_t& r3) {
    asm volatile("ldmatrix.sync.aligned.m8n8.x4.trans.shared.b16 {%0,%1,%2,%3}, [%4];"
                 : "=r"(r0), "=r"(r1), "=r"(r2), "=r"(r3) : "r"(a));
}
__device__ __forceinline__ void mma16816(float* c, const uint32_t* a, uint32_t b0, uint32_t b1) {
    asm volatile(
        "mma.sync.aligned.m16n8k16.row.col.f32.f16.f16.f32 "
        "{%0,%1,%2,%3},{%4,%5,%6,%7},{%8,%9},{%0,%1,%2,%3};"
        : "+f"(c[0]), "+f"(c[1]), "+f"(c[2]), "+f"(c[3])
        : "r"(a[0]), "r"(a[1]), "r"(a[2]), "r"(a[3]), "r"(b0), "r"(b1));
}
__device__ __forceinline__ uint32_t cvta_s(const void* p) {
    uint32_t a;
    asm("{ .reg .u64 t; cvta.to.shared.u64 t, %1; cvt.u32.u64 %0, t; }"
        : "=r"(a) : "l"(p));
    return a;
}

// ------------------------------- K0: prep ----------------------------------
__global__ void k0_prep(const float* __restrict__ f1, const float* __restrict__ f2,
                        const float* __restrict__ gate1, const float* __restrict__ gate2,
                        const float* __restrict__ attr,
                        const float* __restrict__ fc3w, const float* __restrict__ fc1w,
                        const float* __restrict__ box1, const float* __restrict__ box2,
                        const float* __restrict__ fc2w, const float* __restrict__ fc2b) {
    int i = blockIdx.x * 256 + threadIdx.x;
    if (i < 768 * KPAD) {
        int r = i >> 11, k = i & (KPAD - 1);
        float v = 0.f;
        if (k < GD) {
            float g = (r < 384) ? gate1[k] : gate2[k];
            float s = 1.f / (1.f + expf(-g));
            v = ((r < 384) ? f1[(size_t)r * GD + k] : f2[(size_t)(r - 384) * GD + k]) * s;
        }
        g_gf[i] = __float2half_rn(v);
    }
    if (i < KPAD * NPAD) {
        int k = i / NPAD, n = i - k * NPAD;
        g_attrh[i] = __float2half_rn((k < GD && n < 300) ? attr[(size_t)k * 300 + n] : 0.f);
    }
    if (i < OPAD * P3PAD) {               // fc3t[o][p] = fc3_w[p][o]
        int o = i / P3PAD, p = i - o * P3PAD;
        g_fc3t[i] = __float2half_rn((o < 300 && p < 300) ? fc3w[p * 300 + o] : 0.f);
    }
    if (i < 300 * OPAD) {
        int d = i / OPAD, o = i - d * OPAD;
        g_fc1ta[i] = (o < 300) ? fc1w[o * 600 + d] : 0.f;
        g_fc1tb[i] = (o < 300) ? fc1w[o * 600 + 300 + d] : 0.f;
    }
    if (i < 384 * OPAD) {
        int n = i / OPAD, o = i - n * OPAD;
        float pv = 0.f, qv = 0.f;
        if (o < 300) {
#pragma unroll
            for (int j = 0; j < 5; j++) {
                pv += box1[n * 5 + j] * fc2w[o * 10 + j];
                qv += box2[n * 5 + j] * fc2w[o * 10 + 5 + j];
            }
            pv += fc2b[o];
        }
        g_Ph[i] = __float2half_rn(pv);
        g_Qh[i] = __float2half_rn(qv);
    }
}

// ---- K1: partial f = gf @ attrh, fp16 mma, tile 64x64, K-split 2 ----------
__global__ __launch_bounds__(256) void k1_feat() {
    __shared__ __half Af[64 * 72];
    __shared__ __half Bf[64 * 72];
    int tid = threadIdx.x, lane = tid & 31, w = tid >> 5;
    int wm = w >> 1, wn = w & 1;
    int r0 = blockIdx.x * 64, c0 = blockIdx.y * 64;
    int zoff = blockIdx.z * 1024;
    float acc[4][4] = {};
    uint32_t sa = cvta_s(Af), sbB = cvta_s(Bf);
    uint32_t aAddr = sa + ((wm * 16 + (lane & 15)) * 72 + (lane >> 4) * 8) * 2;
    uint32_t bAddr = sbB + ((lane & 15) * 72 + wn * 32 + (lane >> 4) * 8) * 2;

    for (int kc = 0; kc < 16; ++kc) {
        int k0 = zoff + kc * 64;
        __syncthreads();
        for (int i = tid; i < 512; i += 256) {
            int r = i >> 3, u = i & 7;
            *(uint4*)(Af + r * 72 + u * 8) =
                *(const uint4*)(g_gf + (size_t)(r0 + r) * KPAD + k0 + u * 8);
        }
        for (int i = tid; i < 512; i += 256) {
            int k = i >> 3, u = i & 7;
            *(uint4*)(Bf + k * 72 + u * 8) =
                *(const uint4*)(g_attrh + (size_t)(k0 + k) * NPAD + c0 + u * 8);
        }
        __syncthreads();
#pragma unroll
        for (int ks = 0; ks < 4; ++ks) {
            uint32_t a[4];
            ldsm_x4(aAddr + ks * 32, a[0], a[1], a[2], a[3]);
            uint32_t b0, b1, b2, b3, d0, d1, d2, d3;
            ldsm_x4t(bAddr + ks * 2304, b0, b1, b2, b3);
            ldsm_x4t(bAddr + ks * 2304 + 32, d0, d1, d2, d3);
            mma16816(acc[0], a, b0, b1);
            mma16816(acc[1], a, b2, b3);
            mma16816(acc[2], a, d0, d1);
            mma16816(acc[3], a, d2, d3);
        }
    }
    float* dst = blockIdx.z ? g_f2 : g_f;
    int rr = r0 + wm * 16 + (lane >> 2);
    int cbase = c0 + wn * 32 + 2 * (lane & 3);
#pragma unroll
    for (int j = 0; j < 4; ++j) {
        int col = cbase + j * 8;
        if (col < 300) {
            *(float2*)&dst[(size_t)rr * 300 + col] = make_float2(acc[j][0], acc[j][1]);
            *(float2*)&dst[(size_t)(rr + 8) * 300 + col] = make_float2(acc[j][2], acc[j][3]);
        }
    }
}

// --------- K2: U/V[384,304] = (g_f+g_f2) @ fc1t (+fc1_b), fp32 -> fp16 -----
__global__ void k2_uv(const float* __restrict__ fc1b) {
    __shared__ float As[32 * 34];
    __shared__ float Bs[32 * 34];
    int tid = threadIdx.x;
    int tx = tid & 15, ty = tid >> 4;
    int r0 = blockIdx.y * 32, c0 = blockIdx.x * 32;
    bool isU = (r0 < 384);
    const float* Bmat = isU ? g_fc1ta : g_fc1tb;
    float a00 = 0.f, a01 = 0.f, a10 = 0.f, a11 = 0.f;
    for (int kt = 0; kt < 10; ++kt) {
        int k0 = kt * 32;
#pragma unroll
        for (int idx = tid; idx < 1024; idx += 256) {
            int r = idx >> 5, k = idx & 31;
            int gk = k0 + k;
            As[k * 34 + r] = (gk < 300)
                ? g_f[(r0 + r) * 300 + gk] + g_f2[(r0 + r) * 300 + gk] : 0.f;
            int kb = idx >> 5, c = idx & 31;
            int gkb = k0 + kb, gc = c0 + c;
            Bs[kb * 34 + c] = (gkb < 300 && gc < OPAD) ? Bmat[gkb * OPAD + gc] : 0.f;
        }
        __syncthreads();
#pragma unroll
        for (int kk = 0; kk < 32; ++kk) {
            float2 a = *(const float2*)&As[kk * 34 + ty * 2];
            float2 b = *(const float2*)&Bs[kk * 34 + tx * 2];
            a00 += a.x * b.x; a01 += a.x * b.y;
            a10 += a.y * b.x; a11 += a.y * b.y;
        }
        __syncthreads();
    }
    int r = r0 + ty * 2, c = c0 + tx * 2;
    if (c < OPAD) {
        float b0 = 0.f, b1 = 0.f;
        if (isU) {
            if (c < 300) b0 = fc1b[c];
            if (c + 1 < 300) b1 = fc1b[c + 1];
        }
        __half* dst = isU ? g_Uh : g_Vh;
        int rr = isU ? r : r - 384;
        *(half2*)&dst[rr * OPAD + c] = __floats2half2_rn(a00 + b0, a01 + b1);
        *(half2*)&dst[(rr + 1) * OPAD + c] = __floats2half2_rn(a10 + b0, a11 + b1);
    }
}

// ------------------------------- K3: fused main -----------------------------
// 512 thr = 16 warps = 4 row-groups x 4 col-groups; warp tile 32 pairs x 32 p.
// pair tile 128 (8n x 16m). p chunks {128,128,64}. K = o, 19 steps of 16.
constexpr int A_STR = 312;                       // halves (624B rows, conflict-free)
constexpr int B_STR3 = 136;                      // halves (272B rows, conflict-free)
constexpr int OFF_A3 = 1536;
constexpr int OFF_B3 = OFF_A3 + 128 * A_STR * 2; // 81408
constexpr int K3_SMEM = OFF_B3 + OPAD * B_STR3 * 2;  // 164096

__global__ __launch_bounds__(512, 1) void k3_main(const float* __restrict__ wloc,
                                                  const float* __restrict__ fc3b,
                                                  float* __restrict__ out) {
    extern __shared__ char smem[];
    float* sbias = (float*)smem;
    __half* Asm = (__half*)(smem + OFF_A3);
    __half* Bsm = (__half*)(smem + OFF_B3);

    int tid = threadIdx.x, lane = tid & 31, w = tid >> 5;
    int wr = w & 3, wc = w >> 2;                 // 4 row x 4 col groups
    int n0 = blockIdx.x * 8, m0 = blockIdx.y * 16;

    for (int i = tid; i < 320; i += 512) sbias[i] = (i < 300) ? fc3b[i] : 0.f;

    float l0 = wloc[0], l1 = wloc[1];
    float mx = fmaxf(l0, l1);
    float e0 = expf(l0 - mx), e1 = expf(l1 - mx);
    float w0 = e0 / (e0 + e1), w1 = e1 / (e0 + e1);

    // build A tile (128 pairs x 304 k) fp16 from U/V/P/Q
    for (int i = tid; i < 128 * 152; i += 512) {
        int pr = i / 152, o2 = (i - pr * 152) * 2;
        int ni = pr >> 4, mi = pr & 15;
        float2 u = __half22float2(*(const half2*)&g_Uh[(n0 + ni) * OPAD + o2]);
        float2 v = __half22float2(*(const half2*)&g_Vh[(m0 + mi) * OPAD + o2]);
        float2 p = __half22float2(*(const half2*)&g_Ph[(n0 + ni) * OPAD + o2]);
        float2 q = __half22float2(*(const half2*)&g_Qh[(m0 + mi) * OPAD + o2]);
        float rA = w0 * fmaxf(u.x + v.x, 0.f) + w1 * fmaxf(p.x + q.x, 0.f);
        float rB = w0 * fmaxf(u.y + v.y, 0.f) + w1 * fmaxf(p.y + q.y, 0.f);
        *(half2*)&Asm[pr * A_STR + o2] = __floats2half2_rn(rA, rB);
    }

    uint32_t sbase = cvta_s(smem);
    uint32_t aAddr = sbase + OFF_A3 +
                     ((wr * 32 + (lane & 15)) * A_STR + (lane >> 4) * 8) * 2;
    uint32_t bAddr = sbase + OFF_B3 +
                     ((lane & 15) * B_STR3 + wc * 32 + (lane >> 4) * 8) * 2;
    int rbase = lane >> 2, cb = 2 * (lane & 3);

    for (int pc = 0; pc < 3; ++pc) {
        int p0 = pc * 128;
        int width = (pc == 2) ? 64 : 128;
        __syncthreads();  // A ready (pc=0) / prior B reads done
        int wu = width >> 3;
        for (int i = tid; i < 304 * wu; i += 512) {
            int row = i / wu, u = i - row * wu;
            *(uint4*)(Bsm + row * B_STR3 + u * 8) =
                *(const uint4*)(g_fc3t + (size_t)row * P3PAD + p0 + u * 8);
        }
        __syncthreads();

        if (wc * 32 < width) {
            float acc[2][4][4];
#pragma unroll
            for (int x = 0; x < 2; x++)
#pragma unroll
                for (int y = 0; y < 4; y++)
#pragma unroll
                    for (int z = 0; z < 4; z++) acc[x][y][z] = 0.f;

#pragma unroll 1
            for (int ks = 0; ks < 19; ++ks) {
                uint32_t a0[4], a1[4];
                ldsm_x4(aAddr + ks * 32, a0[0], a0[1], a0[2], a0[3]);
                ldsm_x4(aAddr + 16 * A_STR * 2 + ks * 32, a1[0], a1[1], a1[2], a1[3]);
                uint32_t bofs = bAddr + ks * (16 * B_STR3 * 2);
                uint32_t b0, b1, b2, b3, c0r, c1r, c2r, c3r;
                ldsm_x4t(bofs, b0, b1, b2, b3);
                ldsm_x4t(bofs + 32, c0r, c1r, c2r, c3r);
                mma16816(acc[0][0], a0, b0, b1);
                mma16816(acc[0][1], a0, b2, b3);
                mma16816(acc[0][2], a0, c0r, c1r);
                mma16816(acc[0][3], a0, c2r, c3r);
                mma16816(acc[1][0], a1, b0, b1);
                mma16816(acc[1][1], a1, b2, b3);
                mma16816(acc[1][2], a1, c0r, c1r);
                mma16816(acc[1][3], a1, c2r, c3r);
            }

#pragma unroll
            for (int i2 = 0; i2 < 2; ++i2) {
                int pr = wr * 32 + i2 * 16 + rbase;
                int ni = pr >> 4, mi = pr & 15;
                size_t ob1 = ((size_t)(n0 + ni) * 384 + (m0 + mi)) * 300;
                int pr2 = pr + 8;
                int ni2 = pr2 >> 4, mi2 = pr2 & 15;
                size_t ob2 = ((size_t)(n0 + ni2) * 384 + (m0 + mi2)) * 300;
#pragma unroll
                for (int j = 0; j < 4; ++j) {
                    int col = p0 + wc * 32 + j * 8 + cb;
                    if (col < 300) {
                        *(float2*)&out[ob1 + col] = make_float2(
                            acc[i2][j][0] + sbias[col], acc[i2][j][1] + sbias[col + 1]);
                        *(float2*)&out[ob2 + col] = make_float2(
                            acc[i2][j][2] + sbias[col], acc[i2][j][3] + sbias[col + 1]);
                    }
                }
            }
        }
    }
}

// ------------------------------- launch -------------------------------------
extern "C" void kernel_launch(void* const* d_in, const int* in_sizes, int n_in,
                              void* d_out, int out_size) {
    const float* feature1 = (const float*)d_in[0];
    const float* box1     = (const float*)d_in[1];
    const float* feature2 = (const float*)d_in[2];
    const float* box2     = (const float*)d_in[3];
    const float* attr     = (const float*)d_in[4];
    const float* gate1    = (const float*)d_in[5];
    const float* gate2    = (const float*)d_in[6];
    const float* wloc     = (const float*)d_in[7];
    const float* fc1_w    = (const float*)d_in[8];
    const float* fc1_b    = (const float*)d_in[9];
    const float* fc2_w    = (const float*)d_in[10];
    const float* fc2_b    = (const float*)d_in[11];
    const float* fc3_w    = (const float*)d_in[12];
    const float* fc3_b    = (const float*)d_in[13];
    float* out = (float*)d_out;

    static bool attr_set = false;
    if (!attr_set) {
        cudaFuncSetAttribute(k3_main, cudaFuncAttributeMaxDynamicSharedMemorySize, K3_SMEM);
        attr_set = true;
    }

    k0_prep<<<6144, 256>>>(feature1, feature2, gate1, gate2, attr,
                           fc3_w, fc1_w, box1, box2, fc2_w, fc2_b);
    k1_feat<<<dim3(12, 5, 2), 256>>>();
    k2_uv<<<dim3(10, 24), 256>>>(fc1_b);
    k3_main<<<dim3(48, 24), 512, K3_SMEM>>>(wloc, fc3_b, out);
}

// round 8
// speedup vs baseline: 1.9702x; 1.0559x over previous
#include <cuda_runtime.h>
#include <cuda_fp16.h>
#include <cstdint>
#include <math.h>

#define GD 1935       // GATE_DIM
#define OPAD 304      // padded 300 for U/V/P/Q (19*16)
#define KPAD 2048     // padded GATE_DIM for fp16 gemm
#define NPAD 320      // padded 300 cols (attr)
#define P3PAD 336     // fc3 p cols padded to 7*48

// ------------------------- device scratch (no allocs) -----------------------
__device__ __align__(16) __half g_gf[768 * KPAD];       // gated features fp16
__device__ __align__(16) __half g_attrh[KPAD * NPAD];   // attr fp16 [k][n]
__device__ __align__(16) __half g_fc3t[OPAD * P3PAD];   // [o][p] fp16
__device__ __align__(16) float  g_f [768 * 300];        // k1 partial (z=0)
__device__ __align__(16) float  g_f2[768 * 300];        // k1 partial (z=1)
__device__ __align__(16) float  g_fc1ta[300 * OPAD];    // [d][o] = fc1_w[o][d]
__device__ __align__(16) float  g_fc1tb[300 * OPAD];    // [d][o] = fc1_w[o][300+d]
__device__ __align__(16) __half g_Uh[384 * OPAD];
__device__ __align__(16) __half g_Vh[384 * OPAD];
__device__ __align__(16) __half g_Ph[384 * OPAD];
__device__ __align__(16) __half g_Qh[384 * OPAD];

// ------------------------------ helpers -------------------------------------
__device__ __forceinline__ void ldsm_x4(uint32_t a, uint32_t& r0, uint32_t& r1,
                                        uint32_t& r2, uint32_t& r3) {
    asm volatile("ldmatrix.sync.aligned.m8n8.x4.shared.b16 {%0,%1,%2,%3}, [%4];"
                 : "=r"(r0), "=r"(r1), "=r"(r2), "=r"(r3) : "r"(a));
}
__device__ __forceinline__ void ldsm_x4t(uint32_t a, uint32_t& r0, uint32_t& r1,
                                         uint32_t& r2, uint32_t& r3) {
    asm volatile("ldmatrix.sync.aligned.m8n8.x4.trans.shared.b16 {%0,%1,%2,%3}, [%4];"
                 : "=r"(r0), "=r"(r1), "=r"(r2), "=r"(r3) : "r"(a));
}
__device__ __forceinline__ void ldsm_x2t(uint32_t a, uint32_t& r0, uint32_t& r1) {
    asm volatile("ldmatrix.sync.aligned.m8n8.x2.trans.shared.b16 {%0,%1}, [%2];"
                 : "=r"(r0), "=r"(r1) : "r"(a));
}
__device__ __forceinline__ void mma16816(float* c, const uint32_t* a, uint32_t b0, uint32_t b1) {
    asm volatile(
        "mma.sync.aligned.m16n8k16.row.col.f32.f16.f16.f32 "
        "{%0,%1,%2,%3},{%4,%5,%6,%7},{%8,%9},{%0,%1,%2,%3};"
        : "+f"(c[0]), "+f"(c[1]), "+f"(c[2]), "+f"(c[3])
        : "r"(a[0]), "r"(a[1]), "r"(a[2]), "r"(a[3]), "r"(b0), "r"(b1));
}
__device__ __forceinline__ uint32_t cvta_s(const void* p) {
    uint32_t a;
    asm("{ .reg .u64 t; cvta.to.shared.u64 t, %1; cvt.u32.u64 %0, t; }"
        : "=r"(a) : "l"(p));
    return a;
}

// ------------------------------- K0: prep ----------------------------------
__global__ void k0_prep(const float* __restrict__ f1, const float* __restrict__ f2,
                        const float* __restrict__ gate1, const float* __restrict__ gate2,
                        const float* __restrict__ attr,
                        const float* __restrict__ fc3w, const float* __restrict__ fc1w,
                        const float* __restrict__ box1, const float* __restrict__ box2,
                        const float* __restrict__ fc2w, const float* __restrict__ fc2b) {
    int i = blockIdx.x * 256 + threadIdx.x;
    if (i < 768 * KPAD) {
        int r = i >> 11, k = i & (KPAD - 1);
        float v = 0.f;
        if (k < GD) {
            float g = (r < 384) ? gate1[k] : gate2[k];
            float s = 1.f / (1.f + expf(-g));
            v = ((r < 384) ? f1[(size_t)r * GD + k] : f2[(size_t)(r - 384) * GD + k]) * s;
        }
        g_gf[i] = __float2half_rn(v);
    }
    if (i < KPAD * NPAD) {
        int k = i / NPAD, n = i - k * NPAD;
        g_attrh[i] = __float2half_rn((k < GD && n < 300) ? attr[(size_t)k * 300 + n] : 0.f);
    }
    if (i < OPAD * P3PAD) {               // fc3t[o][p] = fc3_w[p][o]
        int o = i / P3PAD, p = i - o * P3PAD;
        g_fc3t[i] = __float2half_rn((o < 300 && p < 300) ? fc3w[p * 300 + o] : 0.f);
    }
    if (i < 300 * OPAD) {
        int d = i / OPAD, o = i - d * OPAD;
        g_fc1ta[i] = (o < 300) ? fc1w[o * 600 + d] : 0.f;
        g_fc1tb[i] = (o < 300) ? fc1w[o * 600 + 300 + d] : 0.f;
    }
    if (i < 384 * OPAD) {
        int n = i / OPAD, o = i - n * OPAD;
        float pv = 0.f, qv = 0.f;
        if (o < 300) {
#pragma unroll
            for (int j = 0; j < 5; j++) {
                pv += box1[n * 5 + j] * fc2w[o * 10 + j];
                qv += box2[n * 5 + j] * fc2w[o * 10 + 5 + j];
            }
            pv += fc2b[o];
        }
        g_Ph[i] = __float2half_rn(pv);
        g_Qh[i] = __float2half_rn(qv);
    }
}

// ---- K1: partial f = gf @ attrh, fp16 mma, tile 64x64, K-split 2 ----------
__global__ __launch_bounds__(256) void k1_feat() {
    __shared__ __half Af[64 * 72];
    __shared__ __half Bf[64 * 72];
    int tid = threadIdx.x, lane = tid & 31, w = tid >> 5;
    int wm = w >> 1, wn = w & 1;
    int r0 = blockIdx.x * 64, c0 = blockIdx.y * 64;
    int zoff = blockIdx.z * 1024;
    float acc[4][4] = {};
    uint32_t sa = cvta_s(Af), sbB = cvta_s(Bf);
    uint32_t aAddr = sa + ((wm * 16 + (lane & 15)) * 72 + (lane >> 4) * 8) * 2;
    uint32_t bAddr = sbB + ((lane & 15) * 72 + wn * 32 + (lane >> 4) * 8) * 2;

    for (int kc = 0; kc < 16; ++kc) {
        int k0 = zoff + kc * 64;
        __syncthreads();
        for (int i = tid; i < 512; i += 256) {
            int r = i >> 3, u = i & 7;
            *(uint4*)(Af + r * 72 + u * 8) =
                *(const uint4*)(g_gf + (size_t)(r0 + r) * KPAD + k0 + u * 8);
        }
        for (int i = tid; i < 512; i += 256) {
            int k = i >> 3, u = i & 7;
            *(uint4*)(Bf + k * 72 + u * 8) =
                *(const uint4*)(g_attrh + (size_t)(k0 + k) * NPAD + c0 + u * 8);
        }
        __syncthreads();
#pragma unroll
        for (int ks = 0; ks < 4; ++ks) {
            uint32_t a[4];
            ldsm_x4(aAddr + ks * 32, a[0], a[1], a[2], a[3]);
            uint32_t b0, b1, b2, b3, d0, d1, d2, d3;
            ldsm_x4t(bAddr + ks * 2304, b0, b1, b2, b3);
            ldsm_x4t(bAddr + ks * 2304 + 32, d0, d1, d2, d3);
            mma16816(acc[0], a, b0, b1);
            mma16816(acc[1], a, b2, b3);
            mma16816(acc[2], a, d0, d1);
            mma16816(acc[3], a, d2, d3);
        }
    }
    float* dst = blockIdx.z ? g_f2 : g_f;
    int rr = r0 + wm * 16 + (lane >> 2);
    int cbase = c0 + wn * 32 + 2 * (lane & 3);
#pragma unroll
    for (int j = 0; j < 4; ++j) {
        int col = cbase + j * 8;
        if (col < 300) {
            *(float2*)&dst[(size_t)rr * 300 + col] = make_float2(acc[j][0], acc[j][1]);
            *(float2*)&dst[(size_t)(rr + 8) * 300 + col] = make_float2(acc[j][2], acc[j][3]);
        }
    }
}

// --------- K2: U/V[384,304] = (g_f+g_f2) @ fc1t (+fc1_b), fp32 -> fp16 -----
__global__ void k2_uv(const float* __restrict__ fc1b) {
    __shared__ float As[32 * 34];
    __shared__ float Bs[32 * 34];
    int tid = threadIdx.x;
    int tx = tid & 15, ty = tid >> 4;
    int r0 = blockIdx.y * 32, c0 = blockIdx.x * 32;
    bool isU = (r0 < 384);
    const float* Bmat = isU ? g_fc1ta : g_fc1tb;
    float a00 = 0.f, a01 = 0.f, a10 = 0.f, a11 = 0.f;
    for (int kt = 0; kt < 10; ++kt) {
        int k0 = kt * 32;
#pragma unroll
        for (int idx = tid; idx < 1024; idx += 256) {
            int r = idx >> 5, k = idx & 31;
            int gk = k0 + k;
            As[k * 34 + r] = (gk < 300)
                ? g_f[(r0 + r) * 300 + gk] + g_f2[(r0 + r) * 300 + gk] : 0.f;
            int kb = idx >> 5, c = idx & 31;
            int gkb = k0 + kb, gc = c0 + c;
            Bs[kb * 34 + c] = (gkb < 300 && gc < OPAD) ? Bmat[gkb * OPAD + gc] : 0.f;
        }
        __syncthreads();
#pragma unroll
        for (int kk = 0; kk < 32; ++kk) {
            float2 a = *(const float2*)&As[kk * 34 + ty * 2];
            float2 b = *(const float2*)&Bs[kk * 34 + tx * 2];
            a00 += a.x * b.x; a01 += a.x * b.y;
            a10 += a.y * b.x; a11 += a.y * b.y;
        }
        __syncthreads();
    }
    int r = r0 + ty * 2, c = c0 + tx * 2;
    if (c < OPAD) {
        float b0 = 0.f, b1 = 0.f;
        if (isU) {
            if (c < 300) b0 = fc1b[c];
            if (c + 1 < 300) b1 = fc1b[c + 1];
        }
        __half* dst = isU ? g_Uh : g_Vh;
        int rr = isU ? r : r - 384;
        *(half2*)&dst[rr * OPAD + c] = __floats2half2_rn(a00 + b0, a01 + b1);
        *(half2*)&dst[(rr + 1) * OPAD + c] = __floats2half2_rn(a10 + b0, a11 + b1);
    }
}

// ------------------------------- K3: fused main -----------------------------
// 256 thr (8 warps), 2 CTAs/SM. Warps: 4 row-groups (32 pairs) x 2 col-groups
// (24 p). Block tile 128 pairs x 48-p chunks (7 chunks). K = o, 19x16.
// A: 608B rows + bit-4 XOR swizzle (conflict-free ldsm). B: 112B rows.
constexpr int OFF_A3 = 1536;
constexpr int OFF_B3 = OFF_A3 + 128 * 608;           // 79360
constexpr int K3_SMEM = OFF_B3 + 304 * 112;          // 113408

__global__ __launch_bounds__(256, 2) void k3_main(const float* __restrict__ wloc,
                                                  const float* __restrict__ fc3b,
                                                  float* __restrict__ out) {
    extern __shared__ char smem[];
    float* sbias = (float*)smem;
    char* Asm = smem + OFF_A3;
    __half* Bsm = (__half*)(smem + OFF_B3);

    int tid = threadIdx.x, lane = tid & 31, w = tid >> 5;
    int wr = w & 3, wc = w >> 2;                 // 4 row x 2 col groups
    int n0 = blockIdx.x * 8, m0 = blockIdx.y * 16;

    for (int i = tid; i < 320; i += 256) sbias[i] = (i < 300) ? fc3b[i] : 0.f;

    float l0 = wloc[0], l1 = wloc[1];
    float mx = fmaxf(l0, l1);
    float e0 = expf(l0 - mx), e1 = expf(l1 - mx);
    float w0 = e0 / (e0 + e1), w1 = e1 / (e0 + e1);

    // build A tile (128 pairs x 304 k) fp16, 608B rows, bit-4 XOR swizzle
    for (int i = tid; i < 128 * 152; i += 256) {
        int pr = i / 152, o2 = (i - pr * 152) * 2;   // o2: even half index
        int ni = pr >> 4, mi = pr & 15;
        float2 u = __half22float2(*(const half2*)&g_Uh[(n0 + ni) * OPAD + o2]);
        float2 v = __half22float2(*(const half2*)&g_Vh[(m0 + mi) * OPAD + o2]);
        float2 p = __half22float2(*(const half2*)&g_Ph[(n0 + ni) * OPAD + o2]);
        float2 q = __half22float2(*(const half2*)&g_Qh[(m0 + mi) * OPAD + o2]);
        float rA = w0 * fmaxf(u.x + v.x, 0.f) + w1 * fmaxf(p.x + q.x, 0.f);
        float rB = w0 * fmaxf(u.y + v.y, 0.f) + w1 * fmaxf(p.y + q.y, 0.f);
        uint32_t boff = (uint32_t)pr * 608 + (((uint32_t)o2 * 2) ^ (((pr >> 2) & 1u) << 4));
        *(half2*)(Asm + boff) = __floats2half2_rn(rA, rB);
    }

    uint32_t sbase = cvta_s(smem);
    int arow = wr * 32 + (lane & 15);
    uint32_t aAddr = sbase + OFF_A3 + (uint32_t)arow * 608 +
                     ((((uint32_t)lane >> 4) << 4) ^ ((((uint32_t)arow >> 2) & 1u) << 4));
    uint32_t bAddr = sbase + OFF_B3 +
                     ((lane & 15) * 112) + wc * 48 + ((lane >> 4) << 4);
    int rbase = lane >> 2, cb = 2 * (lane & 3);

    for (int pc = 0; pc < 7; ++pc) {
        int p0 = pc * 48;
        __syncthreads();  // A ready (pc=0) / prior B reads + staging done
        for (int i = tid; i < 304 * 6; i += 256) {
            int row = i / 6, u = i - row * 6;
            *(uint4*)((char*)Bsm + row * 112 + u * 16) =
                *(const uint4*)(g_fc3t + (size_t)row * P3PAD + p0 + u * 8);
        }
        __syncthreads();

        float acc[2][3][4];
#pragma unroll
        for (int x = 0; x < 2; x++)
#pragma unroll
            for (int y = 0; y < 3; y++)
#pragma unroll
                for (int z = 0; z < 4; z++) acc[x][y][z] = 0.f;

#pragma unroll 1
        for (int ks = 0; ks < 19; ++ks) {
            uint32_t a0[4], a1[4];
            ldsm_x4(aAddr + ks * 32, a0[0], a0[1], a0[2], a0[3]);
            ldsm_x4(aAddr + 16 * 608 + ks * 32, a1[0], a1[1], a1[2], a1[3]);
            uint32_t bofs = bAddr + ks * (16 * 112);
            uint32_t b0, b1, b2, b3, c0r, c1r;
            ldsm_x4t(bofs, b0, b1, b2, b3);
            ldsm_x2t(bofs + 32, c0r, c1r);
            mma16816(acc[0][0], a0, b0, b1);
            mma16816(acc[0][1], a0, b2, b3);
            mma16816(acc[0][2], a0, c0r, c1r);
            mma16816(acc[1][0], a1, b0, b1);
            mma16816(acc[1][1], a1, b2, b3);
            mma16816(acc[1][2], a1, c0r, c1r);
        }

#pragma unroll
        for (int i2 = 0; i2 < 2; ++i2) {
            int pr = wr * 32 + i2 * 16 + rbase;
            int ni = pr >> 4, mi = pr & 15;
            size_t ob1 = ((size_t)(n0 + ni) * 384 + (m0 + mi)) * 300;
            int pr2 = pr + 8;
            int ni2 = pr2 >> 4, mi2 = pr2 & 15;
            size_t ob2 = ((size_t)(n0 + ni2) * 384 + (m0 + mi2)) * 300;
#pragma unroll
            for (int j = 0; j < 3; ++j) {
                int col = p0 + wc * 24 + j * 8 + cb;
                if (col < 300) {
                    *(float2*)&out[ob1 + col] = make_float2(
                        acc[i2][j][0] + sbias[col], acc[i2][j][1] + sbias[col + 1]);
                    *(float2*)&out[ob2 + col] = make_float2(
                        acc[i2][j][2] + sbias[col], acc[i2][j][3] + sbias[col + 1]);
                }
            }
        }
    }
}

// ------------------------------- launch -------------------------------------
extern "C" void kernel_launch(void* const* d_in, const int* in_sizes, int n_in,
                              void* d_out, int out_size) {
    const float* feature1 = (const float*)d_in[0];
    const float* box1     = (const float*)d_in[1];
    const float* feature2 = (const float*)d_in[2];
    const float* box2     = (const float*)d_in[3];
    const float* attr     = (const float*)d_in[4];
    const float* gate1    = (const float*)d_in[5];
    const float* gate2    = (const float*)d_in[6];
    const float* wloc     = (const float*)d_in[7];
    const float* fc1_w    = (const float*)d_in[8];
    const float* fc1_b    = (const float*)d_in[9];
    const float* fc2_w    = (const float*)d_in[10];
    const float* fc2_b    = (const float*)d_in[11];
    const float* fc3_w    = (const float*)d_in[12];
    const float* fc3_b    = (const float*)d_in[13];
    float* out = (float*)d_out;

    static bool attr_set = false;
    if (!attr_set) {
        cudaFuncSetAttribute(k3_main, cudaFuncAttributeMaxDynamicSharedMemorySize, K3_SMEM);
        attr_set = true;
    }

    k0_prep<<<6144, 256>>>(feature1, feature2, gate1, gate2, attr,
                           fc3_w, fc1_w, box1, box2, fc2_w, fc2_b);
    k1_feat<<<dim3(12, 5, 2), 256>>>();
    k2_uv<<<dim3(10, 24), 256>>>(fc1_b);
    k3_main<<<dim3(48, 24), 256, K3_SMEM>>>(wloc, fc3_b, out);
}

// round 9
// speedup vs baseline: 1.9905x; 1.0103x over previous
#include <cuda_runtime.h>
#include <cuda_fp16.h>
#include <cstdint>
#include <math.h>

#define GD 1935       // GATE_DIM
#define OPAD 304      // padded 300 for U/V/P/Q (19*16)
#define KPAD 2048     // padded GATE_DIM for fp16 gemm
#define NPAD 320      // padded 300 cols (attr)
#define P3PAD 336     // fc3 p cols padded to 7*48

// ------------------------- device scratch (no allocs) -----------------------
__device__ __align__(16) __half g_gf[768 * KPAD];       // gated features fp16
__device__ __align__(16) __half g_attrh[KPAD * NPAD];   // attr fp16 [k][n]
__device__ __align__(16) __half g_fc3t[OPAD * P3PAD];   // [o][p] fp16
__device__ __align__(16) float  g_f [768 * 300];        // k1 partial (z=0)
__device__ __align__(16) float  g_f2[768 * 300];        // k1 partial (z=1)
__device__ __align__(16) float  g_fc1ta[300 * OPAD];    // [d][o] = fc1_w[o][d]
__device__ __align__(16) float  g_fc1tb[300 * OPAD];    // [d][o] = fc1_w[o][300+d]
__device__ __align__(16) __half g_Uh[384 * OPAD];
__device__ __align__(16) __half g_Vh[384 * OPAD];
__device__ __align__(16) __half g_Ph[384 * OPAD];
__device__ __align__(16) __half g_Qh[384 * OPAD];

// ------------------------------ helpers -------------------------------------
__device__ __forceinline__ void ldsm_x4(uint32_t a, uint32_t& r0, uint32_t& r1,
                                        uint32_t& r2, uint32_t& r3) {
    asm volatile("ldmatrix.sync.aligned.m8n8.x4.shared.b16 {%0,%1,%2,%3}, [%4];"
                 : "=r"(r0), "=r"(r1), "=r"(r2), "=r"(r3) : "r"(a));
}
__device__ __forceinline__ void ldsm_x4t(uint32_t a, uint32_t& r0, uint32_t& r1,
                                         uint32_t& r2, uint32_t& r3) {
    asm volatile("ldmatrix.sync.aligned.m8n8.x4.trans.shared.b16 {%0,%1,%2,%3}, [%4];"
                 : "=r"(r0), "=r"(r1), "=r"(r2), "=r"(r3) : "r"(a));
}
__device__ __forceinline__ void ldsm_x2t(uint32_t a, uint32_t& r0, uint32_t& r1) {
    asm volatile("ldmatrix.sync.aligned.m8n8.x2.trans.shared.b16 {%0,%1}, [%2];"
                 : "=r"(r0), "=r"(r1) : "r"(a));
}
__device__ __forceinline__ void mma16816(float* c, const uint32_t* a, uint32_t b0, uint32_t b1) {
    asm volatile(
        "mma.sync.aligned.m16n8k16.row.col.f32.f16.f16.f32 "
        "{%0,%1,%2,%3},{%4,%5,%6,%7},{%8,%9},{%0,%1,%2,%3};"
        : "+f"(c[0]), "+f"(c[1]), "+f"(c[2]), "+f"(c[3])
        : "r"(a[0]), "r"(a[1]), "r"(a[2]), "r"(a[3]), "r"(b0), "r"(b1));
}
__device__ __forceinline__ uint32_t cvta_s(const void* p) {
    uint32_t a;
    asm("{ .reg .u64 t; cvta.to.shared.u64 t, %1; cvt.u32.u64 %0, t; }"
        : "=r"(a) : "l"(p));
    return a;
}

// ------------------------------- K0: prep ----------------------------------
__global__ void k0_prep(const float* __restrict__ f1, const float* __restrict__ f2,
                        const float* __restrict__ gate1, const float* __restrict__ gate2,
                        const float* __restrict__ attr,
                        const float* __restrict__ fc3w, const float* __restrict__ fc1w,
                        const float* __restrict__ box1, const float* __restrict__ box2,
                        const float* __restrict__ fc2w, const float* __restrict__ fc2b) {
    int i = blockIdx.x * 256 + threadIdx.x;
    if (i < 768 * KPAD) {
        int r = i >> 11, k = i & (KPAD - 1);
        float v = 0.f;
        if (k < GD) {
            float g = (r < 384) ? gate1[k] : gate2[k];
            float s = 1.f / (1.f + expf(-g));
            v = ((r < 384) ? f1[(size_t)r * GD + k] : f2[(size_t)(r - 384) * GD + k]) * s;
        }
        g_gf[i] = __float2half_rn(v);
    }
    if (i < KPAD * NPAD) {
        int k = i / NPAD, n = i - k * NPAD;
        g_attrh[i] = __float2half_rn((k < GD && n < 300) ? attr[(size_t)k * 300 + n] : 0.f);
    }
    if (i < OPAD * P3PAD) {               // fc3t[o][p] = fc3_w[p][o]
        int o = i / P3PAD, p = i - o * P3PAD;
        g_fc3t[i] = __float2half_rn((o < 300 && p < 300) ? fc3w[p * 300 + o] : 0.f);
    }
    if (i < 300 * OPAD) {
        int d = i / OPAD, o = i - d * OPAD;
        g_fc1ta[i] = (o < 300) ? fc1w[o * 600 + d] : 0.f;
        g_fc1tb[i] = (o < 300) ? fc1w[o * 600 + 300 + d] : 0.f;
    }
    if (i < 384 * OPAD) {
        int n = i / OPAD, o = i - n * OPAD;
        float pv = 0.f, qv = 0.f;
        if (o < 300) {
#pragma unroll
            for (int j = 0; j < 5; j++) {
                pv += box1[n * 5 + j] * fc2w[o * 10 + j];
                qv += box2[n * 5 + j] * fc2w[o * 10 + 5 + j];
            }
            pv += fc2b[o];
        }
        g_Ph[i] = __float2half_rn(pv);
        g_Qh[i] = __float2half_rn(qv);
    }
}

// ---- K1: partial f = gf @ attrh, fp16 mma, tile 64x64, K-split 2 ----------
__global__ __launch_bounds__(256) void k1_feat() {
    __shared__ __half Af[64 * 72];
    __shared__ __half Bf[64 * 72];
    int tid = threadIdx.x, lane = tid & 31, w = tid >> 5;
    int wm = w >> 1, wn = w & 1;
    int r0 = blockIdx.x * 64, c0 = blockIdx.y * 64;
    int zoff = blockIdx.z * 1024;
    float acc[4][4] = {};
    uint32_t sa = cvta_s(Af), sbB = cvta_s(Bf);
    uint32_t aAddr = sa + ((wm * 16 + (lane & 15)) * 72 + (lane >> 4) * 8) * 2;
    uint32_t bAddr = sbB + ((lane & 15) * 72 + wn * 32 + (lane >> 4) * 8) * 2;

    for (int kc = 0; kc < 16; ++kc) {
        int k0 = zoff + kc * 64;
        __syncthreads();
        for (int i = tid; i < 512; i += 256) {
            int r = i >> 3, u = i & 7;
            *(uint4*)(Af + r * 72 + u * 8) =
                *(const uint4*)(g_gf + (size_t)(r0 + r) * KPAD + k0 + u * 8);
        }
        for (int i = tid; i < 512; i += 256) {
            int k = i >> 3, u = i & 7;
            *(uint4*)(Bf + k * 72 + u * 8) =
                *(const uint4*)(g_attrh + (size_t)(k0 + k) * NPAD + c0 + u * 8);
        }
        __syncthreads();
#pragma unroll
        for (int ks = 0; ks < 4; ++ks) {
            uint32_t a[4];
            ldsm_x4(aAddr + ks * 32, a[0], a[1], a[2], a[3]);
            uint32_t b0, b1, b2, b3, d0, d1, d2, d3;
            ldsm_x4t(bAddr + ks * 2304, b0, b1, b2, b3);
            ldsm_x4t(bAddr + ks * 2304 + 32, d0, d1, d2, d3);
            mma16816(acc[0], a, b0, b1);
            mma16816(acc[1], a, b2, b3);
            mma16816(acc[2], a, d0, d1);
            mma16816(acc[3], a, d2, d3);
        }
    }
    float* dst = blockIdx.z ? g_f2 : g_f;
    int rr = r0 + wm * 16 + (lane >> 2);
    int cbase = c0 + wn * 32 + 2 * (lane & 3);
#pragma unroll
    for (int j = 0; j < 4; ++j) {
        int col = cbase + j * 8;
        if (col < 300) {
            *(float2*)&dst[(size_t)rr * 300 + col] = make_float2(acc[j][0], acc[j][1]);
            *(float2*)&dst[(size_t)(rr + 8) * 300 + col] = make_float2(acc[j][2], acc[j][3]);
        }
    }
}

// --------- K2: U/V[384,304] = (g_f+g_f2) @ fc1t (+fc1_b), fp32 -> fp16 -----
__global__ void k2_uv(const float* __restrict__ fc1b) {
    __shared__ float As[32 * 34];
    __shared__ float Bs[32 * 34];
    int tid = threadIdx.x;
    int tx = tid & 15, ty = tid >> 4;
    int r0 = blockIdx.y * 32, c0 = blockIdx.x * 32;
    bool isU = (r0 < 384);
    const float* Bmat = isU ? g_fc1ta : g_fc1tb;
    float a00 = 0.f, a01 = 0.f, a10 = 0.f, a11 = 0.f;
    for (int kt = 0; kt < 10; ++kt) {
        int k0 = kt * 32;
#pragma unroll
        for (int idx = tid; idx < 1024; idx += 256) {
            int r = idx >> 5, k = idx & 31;
            int gk = k0 + k;
            As[k * 34 + r] = (gk < 300)
                ? g_f[(r0 + r) * 300 + gk] + g_f2[(r0 + r) * 300 + gk] : 0.f;
            int kb = idx >> 5, c = idx & 31;
            int gkb = k0 + kb, gc = c0 + c;
            Bs[kb * 34 + c] = (gkb < 300 && gc < OPAD) ? Bmat[gkb * OPAD + gc] : 0.f;
        }
        __syncthreads();
#pragma unroll
        for (int kk = 0; kk < 32; ++kk) {
            float2 a = *(const float2*)&As[kk * 34 + ty * 2];
            float2 b = *(const float2*)&Bs[kk * 34 + tx * 2];
            a00 += a.x * b.x; a01 += a.x * b.y;
            a10 += a.y * b.x; a11 += a.y * b.y;
        }
        __syncthreads();
    }
    int r = r0 + ty * 2, c = c0 + tx * 2;
    if (c < OPAD) {
        float b0 = 0.f, b1 = 0.f;
        if (isU) {
            if (c < 300) b0 = fc1b[c];
            if (c + 1 < 300) b1 = fc1b[c + 1];
        }
        __half* dst = isU ? g_Uh : g_Vh;
        int rr = isU ? r : r - 384;
        *(half2*)&dst[rr * OPAD + c] = __floats2half2_rn(a00 + b0, a01 + b1);
        *(half2*)&dst[(rr + 1) * OPAD + c] = __floats2half2_rn(a10 + b0, a11 + b1);
    }
}

// ------------------------------- K3: fused main -----------------------------
// 256 thr (8 warps), 2 CTAs/SM. Warps: 4 row-groups (32 pairs) x 2 col-groups
// (24 p). Block tile 128 pairs x 48-p chunks (7 chunks). K = o, 19x16.
// A: 608B rows + bit-4 XOR swizzle. B: 112B rows. K-loop software-pipelined.
constexpr int OFF_A3 = 1536;
constexpr int OFF_B3 = OFF_A3 + 128 * 608;           // 79360
constexpr int K3_SMEM = OFF_B3 + 304 * 112;          // 113408

__global__ __launch_bounds__(256, 2) void k3_main(const float* __restrict__ wloc,
                                                  const float* __restrict__ fc3b,
                                                  float* __restrict__ out) {
    extern __shared__ char smem[];
    float* sbias = (float*)smem;
    char* Asm = smem + OFF_A3;
    __half* Bsm = (__half*)(smem + OFF_B3);

    int tid = threadIdx.x, lane = tid & 31, w = tid >> 5;
    int wr = w & 3, wc = w >> 2;                 // 4 row x 2 col groups
    int n0 = blockIdx.x * 8, m0 = blockIdx.y * 16;

    for (int i = tid; i < 320; i += 256) sbias[i] = (i < 300) ? fc3b[i] : 0.f;

    float l0 = wloc[0], l1 = wloc[1];
    float mx = fmaxf(l0, l1);
    float e0 = expf(l0 - mx), e1 = expf(l1 - mx);
    float w0 = e0 / (e0 + e1), w1 = e1 / (e0 + e1);

    // build A tile (128 pairs x 304 k) fp16, 608B rows, bit-4 XOR swizzle
    for (int i = tid; i < 128 * 152; i += 256) {
        int pr = i / 152, o2 = (i - pr * 152) * 2;
        int ni = pr >> 4, mi = pr & 15;
        float2 u = __half22float2(*(const half2*)&g_Uh[(n0 + ni) * OPAD + o2]);
        float2 v = __half22float2(*(const half2*)&g_Vh[(m0 + mi) * OPAD + o2]);
        float2 p = __half22float2(*(const half2*)&g_Ph[(n0 + ni) * OPAD + o2]);
        float2 q = __half22float2(*(const half2*)&g_Qh[(m0 + mi) * OPAD + o2]);
        float rA = w0 * fmaxf(u.x + v.x, 0.f) + w1 * fmaxf(p.x + q.x, 0.f);
        float rB = w0 * fmaxf(u.y + v.y, 0.f) + w1 * fmaxf(p.y + q.y, 0.f);
        uint32_t boff = (uint32_t)pr * 608 + (((uint32_t)o2 * 2) ^ (((pr >> 2) & 1u) << 4));
        *(half2*)(Asm + boff) = __floats2half2_rn(rA, rB);
    }

    uint32_t sbase = cvta_s(smem);
    int arow = wr * 32 + (lane & 15);
    uint32_t aAddr = sbase + OFF_A3 + (uint32_t)arow * 608 +
                     ((((uint32_t)lane >> 4) << 4) ^ ((((uint32_t)arow >> 2) & 1u) << 4));
    uint32_t bAddr = sbase + OFF_B3 +
                     ((lane & 15) * 112) + wc * 48 + ((lane >> 4) << 4);
    int rbase = lane >> 2, cb = 2 * (lane & 3);

    for (int pc = 0; pc < 7; ++pc) {
        int p0 = pc * 48;
        __syncthreads();  // A ready (pc=0) / prior B reads done
        for (int i = tid; i < 304 * 6; i += 256) {
            int row = i / 6, u = i - row * 6;
            *(uint4*)((char*)Bsm + row * 112 + u * 16) =
                *(const uint4*)(g_fc3t + (size_t)row * P3PAD + p0 + u * 8);
        }
        __syncthreads();

        float acc[2][3][4];
#pragma unroll
        for (int x = 0; x < 2; x++)
#pragma unroll
            for (int y = 0; y < 3; y++)
#pragma unroll
                for (int z = 0; z < 4; z++) acc[x][y][z] = 0.f;

        // ---- software-pipelined K loop: prefetch ks+1 frags during mma(ks) ----
        uint32_t a0[2][4], a1[2][4], bb[2][6];
        ldsm_x4(aAddr, a0[0][0], a0[0][1], a0[0][2], a0[0][3]);
        ldsm_x4(aAddr + 16 * 608, a1[0][0], a1[0][1], a1[0][2], a1[0][3]);
        ldsm_x4t(bAddr, bb[0][0], bb[0][1], bb[0][2], bb[0][3]);
        ldsm_x2t(bAddr + 32, bb[0][4], bb[0][5]);
#pragma unroll
        for (int ks = 0; ks < 19; ++ks) {
            int cur = ks & 1, nxt = cur ^ 1;
            if (ks < 18) {
                uint32_t ao = aAddr + (ks + 1) * 32;
                uint32_t bo = bAddr + (ks + 1) * (16 * 112);
                ldsm_x4(ao, a0[nxt][0], a0[nxt][1], a0[nxt][2], a0[nxt][3]);
                ldsm_x4(ao + 16 * 608, a1[nxt][0], a1[nxt][1], a1[nxt][2], a1[nxt][3]);
                ldsm_x4t(bo, bb[nxt][0], bb[nxt][1], bb[nxt][2], bb[nxt][3]);
                ldsm_x2t(bo + 32, bb[nxt][4], bb[nxt][5]);
            }
            mma16816(acc[0][0], a0[cur], bb[cur][0], bb[cur][1]);
            mma16816(acc[0][1], a0[cur], bb[cur][2], bb[cur][3]);
            mma16816(acc[0][2], a0[cur], bb[cur][4], bb[cur][5]);
            mma16816(acc[1][0], a1[cur], bb[cur][0], bb[cur][1]);
            mma16816(acc[1][1], a1[cur], bb[cur][2], bb[cur][3]);
            mma16816(acc[1][2], a1[cur], bb[cur][4], bb[cur][5]);
        }

#pragma unroll
        for (int i2 = 0; i2 < 2; ++i2) {
            int pr = wr * 32 + i2 * 16 + rbase;
            int ni = pr >> 4, mi = pr & 15;
            size_t ob1 = ((size_t)(n0 + ni) * 384 + (m0 + mi)) * 300;
            int pr2 = pr + 8;
            int ni2 = pr2 >> 4, mi2 = pr2 & 15;
            size_t ob2 = ((size_t)(n0 + ni2) * 384 + (m0 + mi2)) * 300;
#pragma unroll
            for (int j = 0; j < 3; ++j) {
                int col = p0 + wc * 24 + j * 8 + cb;
                if (col < 300) {
                    *(float2*)&out[ob1 + col] = make_float2(
                        acc[i2][j][0] + sbias[col], acc[i2][j][1] + sbias[col + 1]);
                    *(float2*)&out[ob2 + col] = make_float2(
                        acc[i2][j][2] + sbias[col], acc[i2][j][3] + sbias[col + 1]);
                }
            }
        }
    }
}

// ------------------------------- launch -------------------------------------
extern "C" void kernel_launch(void* const* d_in, const int* in_sizes, int n_in,
                              void* d_out, int out_size) {
    const float* feature1 = (const float*)d_in[0];
    const float* box1     = (const float*)d_in[1];
    const float* feature2 = (const float*)d_in[2];
    const float* box2     = (const float*)d_in[3];
    const float* attr     = (const float*)d_in[4];
    const float* gate1    = (const float*)d_in[5];
    const float* gate2    = (const float*)d_in[6];
    const float* wloc     = (const float*)d_in[7];
    const float* fc1_w    = (const float*)d_in[8];
    const float* fc1_b    = (const float*)d_in[9];
    const float* fc2_w    = (const float*)d_in[10];
    const float* fc2_b    = (const float*)d_in[11];
    const float* fc3_w    = (const float*)d_in[12];
    const float* fc3_b    = (const float*)d_in[13];
    float* out = (float*)d_out;

    static bool attr_set = false;
    if (!attr_set) {
        cudaFuncSetAttribute(k3_main, cudaFuncAttributeMaxDynamicSharedMemorySize, K3_SMEM);
        attr_set = true;
    }

    k0_prep<<<6144, 256>>>(feature1, feature2, gate1, gate2, attr,
                           fc3_w, fc1_w, box1, box2, fc2_w, fc2_b);
    k1_feat<<<dim3(12, 5, 2), 256>>>();
    k2_uv<<<dim3(10, 24), 256>>>(fc1_b);
    k3_main<<<dim3(48, 24), 256, K3_SMEM>>>(wloc, fc3_b, out);
}